// round 1
// baseline (speedup 1.0000x reference)
#include <cuda_runtime.h>
#include <cuda_bf16.h>

// Contour_to_mask: winding-number mask.
// out[i,j] = clamp( sum_n tanh(K*cross_n) * acos(clamp(cos_n, -1+eps, 1-eps)) / (2*pi), 0, 1 )
// where diff_n = contour[n] - p, roll_n = contour[n+1] - p (cyclic),
// cross_n = diff.y*roll.x - diff.x*roll.y, cos_n = dot(diff,roll)/(|diff||roll|).
// Pixel p = (i/512, j/512) with idx = i*512 + j (ij meshgrid indexing).

#define MSIZE 512
#define NPTS  128
#define KCONST 100000.0f
#define EPSC   1e-5f

__global__ void __launch_bounds__(256, 8)
contour_mask_kernel(const float* __restrict__ contour, float* __restrict__ out) {
    __shared__ float2 c[NPTS];
    const int t = threadIdx.x;
    if (t < NPTS) {
        c[t] = reinterpret_cast<const float2*>(contour)[t];
    }
    __syncthreads();

    const int idx = blockIdx.x * 256 + t;
    const float px = (float)(idx >> 9)   * (1.0f / (float)MSIZE);
    const float py = (float)(idx & 511)  * (1.0f / (float)MSIZE);

    // diff for edge start 0; carried across iterations (roll_j == diff_{j+1})
    float dx = c[0].x - px;
    float dy = c[0].y - py;
    float d2 = fmaf(dx, dx, dy * dy);

    float sum = 0.0f;

#pragma unroll 8
    for (int j = 0; j < NPTS; ++j) {
        const float2 cn = c[(j + 1) & (NPTS - 1)];
        const float rx = cn.x - px;
        const float ry = cn.y - py;

        // cross = prod[1]-prod[0] = dy*rx - dx*ry  (matches reference ordering)
        const float cross = fmaf(dy, rx, -(dx * ry));
        const float dotp  = fmaf(dx, rx,  dy * ry);
        const float r2    = fmaf(rx, rx,  ry * ry);

        float cosang = dotp * rsqrtf(d2 * r2);
        cosang = fminf(fmaxf(cosang, -1.0f + EPSC), 1.0f - EPSC);

        const float ang = acosf(cosang);
        const float sgn = tanhf(KCONST * cross);

        sum = fmaf(sgn, ang, sum);

        // carry: this edge's roll is next edge's diff
        dx = rx; dy = ry; d2 = r2;
    }

    const float v = sum * (float)(1.0 / (2.0 * 3.14159265358979323846));
    out[idx] = fminf(fmaxf(v, 0.0f), 1.0f);
}

extern "C" void kernel_launch(void* const* d_in, const int* in_sizes, int n_in,
                              void* d_out, int out_size) {
    const float* contour = (const float*)d_in[0];
    float* out = (float*)d_out;
    const int total = MSIZE * MSIZE;
    contour_mask_kernel<<<total / 256, 256>>>(contour, out);
}

// round 2
// speedup vs baseline: 1.3765x; 1.3765x over previous
#include <cuda_runtime.h>
#include <cuda_bf16.h>

// Contour_to_mask: winding-number mask, 512x512 pixels x 128 contour points.
// out[i,j] = clamp( sum_n tanh(K*cross_n) * acos(clamp(cos_n, -1+eps, 1-eps)) / (2*pi), 0, 1 )
// diff_n = contour[n] - p, roll_n = contour[n+1] - p (cyclic),
// cross_n = diff.y*roll.x - diff.x*roll.y, cos_n = dot/( |diff||roll| ).
// p = (i/512, j/512), idx = i*512 + j.
//
// Optimization: 2 pixels/thread (same row -> rx, dx*rx, rx*rx, LDS shared),
// HW tanh.approx.f32, branch-free polynomial acos, carried diff (roll_j == diff_{j+1}).

#define MSIZE 512
#define NPTS  128
#define KCONST 100000.0f
#define EPSC   1e-5f
#define INV2PI 0.15915494309189535f
#define PI_F   3.14159265358979323846f

// acos via A&S 4.4.45-style 7-term poly: acos(|x|) = sqrt(1-|x|)*P(|x|), abs err ~1e-7.
// Requires |x| <= 1 - 1e-5 (guaranteed by the clamp), so 1-|x| > 0.
__device__ __forceinline__ float facos(float x) {
    float ax = fabsf(x);
    float t  = 1.0f - ax;
    float s  = t * rsqrtf(t);                    // sqrt(1-ax), MUFU.RSQ + 2 mul
    float p  = fmaf(-0.0012624911f, ax, 0.0066700901f);
    p = fmaf(p, ax, -0.0170881256f);
    p = fmaf(p, ax,  0.0308918810f);
    p = fmaf(p, ax, -0.0501743046f);
    p = fmaf(p, ax,  0.0889789874f);
    p = fmaf(p, ax, -0.2145988016f);
    p = fmaf(p, ax,  1.5707963050f);
    float r = s * p;
    return (x < 0.0f) ? (PI_F - r) : r;
}

__device__ __forceinline__ float ftanh(float x) {
    float r;
    asm("tanh.approx.f32 %0, %1;" : "=f"(r) : "f"(x));
    return r;
}

__global__ void __launch_bounds__(256)
contour_mask_kernel(const float* __restrict__ contour, float* __restrict__ out) {
    __shared__ float2 c[NPTS];
    const int t = threadIdx.x;
    if (t < NPTS) {
        c[t] = reinterpret_cast<const float2*>(contour)[t];
    }
    __syncthreads();

    // One block per row. Thread handles columns t and t+256.
    const int row = blockIdx.x;
    const float px  = (float)row       * (1.0f / (float)MSIZE);
    const float py0 = (float)t         * (1.0f / (float)MSIZE);
    const float py1 = (float)(t + 256) * (1.0f / (float)MSIZE);

    // Carried diff for edge start 0 (roll of edge j == diff of edge j+1).
    float dx  = c[0].x - px;
    float dy0 = c[0].y - py0;
    float dy1 = c[0].y - py1;
    float d20 = fmaf(dx, dx, dy0 * dy0);
    float d21 = fmaf(dx, dx, dy1 * dy1);

    float sum0 = 0.0f;
    float sum1 = 0.0f;

#pragma unroll 8
    for (int j = 0; j < NPTS; ++j) {
        const float2 cn = c[(j + 1) & (NPTS - 1)];
        const float rx   = cn.x - px;          // shared between both pixels
        const float ry0  = cn.y - py0;
        const float ry1  = cn.y - py1;
        const float rxx  = rx * rx;            // shared
        const float dxrx = dx * rx;            // shared

        const float r20 = fmaf(ry0, ry0, rxx);
        const float r21 = fmaf(ry1, ry1, rxx);

        // cross = dy*rx - dx*ry  (reference ordering: prod[1] - prod[0])
        const float cross0 = fmaf(dy0, rx, -(dx * ry0));
        const float cross1 = fmaf(dy1, rx, -(dx * ry1));
        const float dot0   = fmaf(dy0, ry0, dxrx);
        const float dot1   = fmaf(dy1, ry1, dxrx);

        float cos0 = dot0 * rsqrtf(d20 * r20);
        float cos1 = dot1 * rsqrtf(d21 * r21);
        cos0 = fminf(fmaxf(cos0, -1.0f + EPSC), 1.0f - EPSC);
        cos1 = fminf(fmaxf(cos1, -1.0f + EPSC), 1.0f - EPSC);

        const float ang0 = facos(cos0);
        const float ang1 = facos(cos1);
        const float sg0  = ftanh(KCONST * cross0);
        const float sg1  = ftanh(KCONST * cross1);

        sum0 = fmaf(sg0, ang0, sum0);
        sum1 = fmaf(sg1, ang1, sum1);

        // carry: this edge's roll is next edge's diff
        dx = rx; dy0 = ry0; dy1 = ry1; d20 = r20; d21 = r21;
    }

    const int base = row * MSIZE + t;
    out[base]       = fminf(fmaxf(sum0 * INV2PI, 0.0f), 1.0f);
    out[base + 256] = fminf(fmaxf(sum1 * INV2PI, 0.0f), 1.0f);
}

extern "C" void kernel_launch(void* const* d_in, const int* in_sizes, int n_in,
                              void* d_out, int out_size) {
    const float* contour = (const float*)d_in[0];
    float* out = (float*)d_out;
    contour_mask_kernel<<<MSIZE, 256>>>(contour, out);
}